// round 6
// baseline (speedup 1.0000x reference)
#include <cuda_runtime.h>

namespace {
constexpr int kH = 8;
constexpr int kB = 32;
constexpr int kN = 512;
constexpr int kD = 256;
constexpr int kd = 32;
constexpr int kBN = kB * kN;               // 16384
constexpr int kHWaveElems = kB * kN * kD;  // 4,194,304
// fused smem: Qs 8192 + KV 9216 + Sc 8448 + W1 256 + W2 128 + b1 16 + b2 8
constexpr int kFusedF = 8192 + 9216 + 8448 + 256 + 128 + 16 + 8;
constexpr size_t kFusedSmem = kFusedF * sizeof(float);  // 105056 B
}

using ull = unsigned long long;

__device__ __forceinline__ void fma2(ull& d, ull a, ull b) {
  asm("fma.rn.f32x2 %0, %1, %2, %0;" : "+l"(d) : "l"(a), "l"(b));
}
__device__ __forceinline__ void mul2(ull& d, ull a) {
  asm("mul.rn.f32x2 %0, %0, %1;" : "+l"(d) : "l"(a));
}
__device__ __forceinline__ ull pack2(float lo, float hi) {
  ull r;
  asm("mov.b64 %0, {%1, %2};" : "=l"(r) : "f"(lo), "f"(hi));
  return r;
}
__device__ __forceinline__ float2 unpack2(ull v) {
  float2 r;
  asm("mov.b64 {%0, %1}, %2;" : "=f"(r.x), "=f"(r.y) : "l"(v));
  return r;
}

// Scratch (device globals: allocation-free rule)
__device__ float g_Q[kH * kBN * kd];
__device__ float g_K[kH * kBN * kd];
__device__ float g_V[kH * kBN * kd];
__device__ float g_heads[kH * kBN * kd];

// ---------------------------------------------------------------------------
// GEMM body: 128x128 block, 256 threads, per-thread 8x8 (32 FMA2 : 4 LDS.128
// per k-step -> 4 FMA/float = crossbar limit). As transposed [kk][row] (+4 pad),
// Bs natural [kk][col]. Register double-buffered gmem loads, k-chunk 16.
// ---------------------------------------------------------------------------
#define GEMM_DECL                                  \
  __shared__ __align__(16) float As[16 * 132];     \
  __shared__ __align__(16) float Bs[16 * 128];     \
  const int t = threadIdx.x;                       \
  const int tx = t & 15, ty = t >> 4;              \
  const int arow0 = t >> 2, akq0 = (t & 3) * 4;    \
  const int arow1 = arow0 + 64;                    \
  const int bkk0 = t >> 5, bc4 = (t & 31) * 4;     \
  const int bkk1 = bkk0 + 8;                       \
  ull acc2[8][4];                                  \
  _Pragma("unroll") for (int r = 0; r < 8; r++)    \
  _Pragma("unroll") for (int c = 0; c < 4; c++) acc2[r][c] = 0ULL;

#define GEMM_STS(ra0, ra1, rb0, rb1)                            \
  {                                                             \
    const float a0v[4] = {ra0.x, ra0.y, ra0.z, ra0.w};          \
    const float a1v[4] = {ra1.x, ra1.y, ra1.z, ra1.w};          \
    _Pragma("unroll") for (int j = 0; j < 4; j++) {             \
      As[(akq0 + j) * 132 + arow0] = a0v[j];                    \
      As[(akq0 + j) * 132 + arow1] = a1v[j];                    \
    }                                                           \
    *(float4*)&Bs[bkk0 * 128 + bc4] = rb0;                      \
    *(float4*)&Bs[bkk1 * 128 + bc4] = rb1;                      \
  }

#define GEMM_COMPUTE                                            \
  _Pragma("unroll") for (int kk = 0; kk < 16; kk++) {           \
    const float4 a0 = *(const float4*)&As[kk * 132 + ty * 8];   \
    const float4 a1 = *(const float4*)&As[kk * 132 + ty * 8 + 4]; \
    const ulonglong2 bq0 = *(const ulonglong2*)&Bs[kk * 128 + tx * 8]; \
    const ulonglong2 bq1 = *(const ulonglong2*)&Bs[kk * 128 + tx * 8 + 4]; \
    const float aa[8] = {a0.x, a0.y, a0.z, a0.w, a1.x, a1.y, a1.z, a1.w}; \
    _Pragma("unroll") for (int r = 0; r < 8; r++) {             \
      const ull ap = pack2(aa[r], aa[r]);                       \
      fma2(acc2[r][0], ap, bq0.x);                              \
      fma2(acc2[r][1], ap, bq0.y);                              \
      fma2(acc2[r][2], ap, bq1.x);                              \
      fma2(acc2[r][3], ap, bq1.y);                              \
    }                                                           \
  }

// ---------------------------------------------------------------------------
// K1: QKV projection [16384 x 256] x [256 x 768]. grid (6, 128).
// ---------------------------------------------------------------------------
__global__ __launch_bounds__(256, 2) void qkv_kernel(
    const float* __restrict__ A, const float* __restrict__ Wq,
    const float* __restrict__ Wk, const float* __restrict__ Wv) {
  GEMM_DECL
  const int c0 = blockIdx.x * 128;
  const int row0 = blockIdx.y * 128;
  const int which = c0 >> 8;
  const float* __restrict__ W = (which == 0) ? Wq : (which == 1) ? Wk : Wv;
  float* __restrict__ O = (which == 0) ? g_Q : (which == 1) ? g_K : g_V;

  const int bc = c0 + bc4;
  const int bh = (bc >> 5) & 7, bdd = bc & 31;

  float4 ra0 = *(const float4*)&A[(row0 + arow0) * kD + akq0];
  float4 ra1 = *(const float4*)&A[(row0 + arow1) * kD + akq0];
  float4 rb0 = *(const float4*)&W[(bh * 256 + bkk0) * kd + bdd];
  float4 rb1 = *(const float4*)&W[(bh * 256 + bkk1) * kd + bdd];

  for (int k0 = 0; k0 < kD; k0 += 16) {
    GEMM_STS(ra0, ra1, rb0, rb1)
    __syncthreads();
    if (k0 + 16 < kD) {
      ra0 = *(const float4*)&A[(row0 + arow0) * kD + k0 + 16 + akq0];
      ra1 = *(const float4*)&A[(row0 + arow1) * kD + k0 + 16 + akq0];
      rb0 = *(const float4*)&W[(bh * 256 + k0 + 16 + bkk0) * kd + bdd];
      rb1 = *(const float4*)&W[(bh * 256 + k0 + 16 + bkk1) * kd + bdd];
    }
    GEMM_COMPUTE
    __syncthreads();
  }

#pragma unroll
  for (int r = 0; r < 8; r++) {
    const int row = row0 + ty * 8 + r;
#pragma unroll
    for (int cp = 0; cp < 4; cp++) {
      const int oc = c0 + tx * 8 + 2 * cp;
      const int h = (oc >> 5) & 7, dd = oc & 31;
      *(ull*)&O[(h * kBN + row) * kd + dd] = acc2[r][cp];
    }
  }
}

// ---------------------------------------------------------------------------
// K3: output projection [16384 x 256] x [256 x 256]. grid (2, 128).
// ---------------------------------------------------------------------------
__global__ __launch_bounds__(256, 2) void outproj_kernel(
    const float* __restrict__ Wout, float* __restrict__ out) {
  GEMM_DECL
  const int c0 = blockIdx.x * 128;
  const int row0 = blockIdx.y * 128;

  auto ldA = [&](int row, int k) {
    const int h = k >> 5, dd = k & 31;
    return *(const float4*)&g_heads[(h * kBN + row0 + row) * kd + dd];
  };
  float4 ra0 = ldA(arow0, akq0);
  float4 ra1 = ldA(arow1, akq0);
  float4 rb0 = *(const float4*)&Wout[bkk0 * kD + c0 + bc4];
  float4 rb1 = *(const float4*)&Wout[bkk1 * kD + c0 + bc4];

  for (int k0 = 0; k0 < kD; k0 += 16) {
    GEMM_STS(ra0, ra1, rb0, rb1)
    __syncthreads();
    if (k0 + 16 < kD) {
      ra0 = ldA(arow0, k0 + 16 + akq0);
      ra1 = ldA(arow1, k0 + 16 + akq0);
      rb0 = *(const float4*)&Wout[(k0 + 16 + bkk0) * kD + c0 + bc4];
      rb1 = *(const float4*)&Wout[(k0 + 16 + bkk1) * kD + c0 + bc4];
    }
    GEMM_COMPUTE
    __syncthreads();
  }

#pragma unroll
  for (int r = 0; r < 8; r++) {
    const int row = row0 + ty * 8 + r;
#pragma unroll
    for (int cp = 0; cp < 4; cp++)
      *(ull*)&out[row * kD + c0 + tx * 8 + 2 * cp] = acc2[r][cp];
  }
}

// ---------------------------------------------------------------------------
// K2 (fused): scores + MLP + aux passthrough + ONLINE softmax + P@V.
// Never materializes the [H,B,N,N] logits in gmem.
// Grid (16 n-tiles, 32 b), 256 threads, 2 CTA/SM (105KB smem).
// Per m-chunk (32): load K -> scores (role h,m; K row in regs, Q broadcast) ->
// MLP (role nl,mm; aux prefetched under scores) -> load V -> online PV (role h,n).
// ---------------------------------------------------------------------------
__global__ __launch_bounds__(256, 2) void fused_attn_kernel(
    const float* __restrict__ aux, const float* __restrict__ W1,
    const float* __restrict__ b1, const float* __restrict__ W2,
    const float* __restrict__ b2, float* __restrict__ out_aux) {
  extern __shared__ __align__(16) float sm[];
  float* Qs = sm;                 // [8][32][32] flat, broadcast reads only
  float* KV = sm + 8192;          // [8][32][36] K then V, LDS.128-friendly pad
  float* Sc = sm + 8192 + 9216;   // [8][32][33] scores/logits
  float* W1s = Sc + 8448;
  float* W2s = W1s + 256;
  float* b1s = W2s + 128;
  float* b2s = b1s + 16;
  const int n0 = blockIdx.x * 32;
  const int b = blockIdx.y;
  const int t = threadIdx.x;
  const int hr = t >> 5, ln = t & 31;  // role (h, m|n)
  const int nl = t >> 5, mm = t & 31;  // role (n-phase, m) for MLP

  // one-time loads
#pragma unroll
  for (int i = 0; i < 8; i++) {
    const int idx = t + 256 * i;
    const int h = idx >> 8, rem = idx & 255;
    const int n = rem >> 3, d4 = (rem & 7) * 4;
    *(float4*)&Qs[h * 1024 + n * 32 + d4] =
        *(const float4*)&g_Q[((h * kB + b) * kN + n0 + n) * kd + d4];
  }
  W1s[t] = W1[t];
  if (t < 128) W2s[t] = W2[t];
  if (t < 16) b1s[t] = b1[t];
  if (t < 8) b2s[t] = b2[t];

  float M = -1e30f, S = 0.f;
  ull acc2[16];
#pragma unroll
  for (int i = 0; i < 16; i++) acc2[i] = 0ULL;

#pragma unroll 1
  for (int ch = 0; ch < 16; ch++) {
    const int m0 = ch * 32;
    __syncthreads();  // KV & Sc reusable (prev chunk's PV done); Qs ready (ch 0)
    // ---- load K chunk ----
#pragma unroll
    for (int i = 0; i < 8; i++) {
      const int idx = t + 256 * i;
      const int h = idx >> 8, rem = idx & 255;
      const int m = rem >> 3, d4 = (rem & 7) * 4;
      *(float4*)&KV[h * 1152 + m * 36 + d4] =
          *(const float4*)&g_K[((h * kB + b) * kN + m0 + m) * kd + d4];
    }
    __syncthreads();
    // ---- aux prefetch + passthrough (hidden under scores GEMM) ----
    float av[4][8];
#pragma unroll
    for (int p = 0; p < 4; p++) {
      const int n = nl + 8 * p;
#pragma unroll
      for (int h = 0; h < 8; h++) {
        const int gi = ((h * kB + b) * kN + n0 + n) * kN + m0 + mm;
        const float a = aux[gi];
        out_aux[gi] = a;
        av[p][h] = a;
      }
    }
    // ---- scores: role (hr, m=ln); K row in regs, Q broadcast ----
    {
      ulonglong2 kr[8];
#pragma unroll
      for (int i = 0; i < 8; i++)
        kr[i] = *(const ulonglong2*)&KV[hr * 1152 + ln * 36 + i * 4];
#pragma unroll 1
      for (int n = 0; n < 32; n++) {
        const float* qp = &Qs[hr * 1024 + n * 32];
        ull s2 = 0ULL;
#pragma unroll
        for (int i = 0; i < 8; i++) {
          const ulonglong2 q2 = *(const ulonglong2*)(qp + i * 4);
          fma2(s2, q2.x, kr[i].x);
          fma2(s2, q2.y, kr[i].y);
        }
        const float2 sv = unpack2(s2);
        Sc[hr * 1056 + n * 33 + ln] = sv.x + sv.y;
      }
    }
    __syncthreads();
    // ---- MLP: role (nl, mm), x4 position blocking ----
    {
      ull hid2[4][8];
#pragma unroll
      for (int j2 = 0; j2 < 8; j2++) {
        const ull bp = *(const ull*)&b1s[2 * j2];
#pragma unroll
        for (int p = 0; p < 4; p++) hid2[p][j2] = bp;
      }
#pragma unroll
      for (int i = 0; i < 16; i++) {
        ull xp[4];
#pragma unroll
        for (int p = 0; p < 4; p++) {
          const float xv = (i < 8) ? Sc[i * 1056 + (nl + 8 * p) * 33 + mm]
                                   : av[p][i - 8];
          xp[p] = pack2(xv, xv);
        }
#pragma unroll
        for (int j2 = 0; j2 < 8; j2++) {
          const ull w2 = *(const ull*)&W1s[i * 16 + 2 * j2];
#pragma unroll
          for (int p = 0; p < 4; p++) fma2(hid2[p][j2], xp[p], w2);
        }
      }
      ull o2[4][4];
#pragma unroll
      for (int k2 = 0; k2 < 4; k2++) {
        const ull bp = *(const ull*)&b2s[2 * k2];
#pragma unroll
        for (int p = 0; p < 4; p++) o2[p][k2] = bp;
      }
#pragma unroll
      for (int j2 = 0; j2 < 8; j2++) {
#pragma unroll
        for (int p = 0; p < 4; p++) {
          float2 hv = unpack2(hid2[p][j2]);
          hv.x = fmaxf(hv.x, 0.f);
          hv.y = fmaxf(hv.y, 0.f);
          const ull hp0 = pack2(hv.x, hv.x);
          const ull hp1 = pack2(hv.y, hv.y);
#pragma unroll
          for (int k2 = 0; k2 < 4; k2++) {
            fma2(o2[p][k2], hp0, *(const ull*)&W2s[(2 * j2) * 8 + 2 * k2]);
            fma2(o2[p][k2], hp1, *(const ull*)&W2s[(2 * j2 + 1) * 8 + 2 * k2]);
          }
        }
      }
#pragma unroll
      for (int p = 0; p < 4; p++) {
        const int n = nl + 8 * p;
#pragma unroll
        for (int k2 = 0; k2 < 4; k2++) {
          const float2 ov = unpack2(o2[p][k2]);
          Sc[(2 * k2) * 1056 + n * 33 + mm] = ov.x;
          Sc[(2 * k2 + 1) * 1056 + n * 33 + mm] = ov.y;
        }
      }
    }
    // ---- load V chunk (safe: all threads are past the scores phase because
    // the MLP phase began with a __syncthreads; MLP touches only Sc/W1s) ----
#pragma unroll
    for (int i = 0; i < 8; i++) {
      const int idx = t + 256 * i;
      const int h = idx >> 8, rem = idx & 255;
      const int m = rem >> 3, d4 = (rem & 7) * 4;
      *(float4*)&KV[h * 1152 + m * 36 + d4] =
          *(const float4*)&g_V[((h * kB + b) * kN + m0 + m) * kd + d4];
    }
    __syncthreads();  // V + MLP logits visible
    // ---- online softmax + PV: role (hr, n=ln) ----
    {
      float a[32];
#pragma unroll
      for (int i = 0; i < 32; i++) a[i] = Sc[hr * 1056 + ln * 33 + i];
      float cm = a[0];
#pragma unroll
      for (int i = 1; i < 32; i++) cm = fmaxf(cm, a[i]);
      const float newM = fmaxf(M, cm);
      const float sc = __expf(M - newM);
      S *= sc;
      const ull scp = pack2(sc, sc);
#pragma unroll
      for (int i = 0; i < 16; i++) mul2(acc2[i], scp);
#pragma unroll 1
      for (int m = 0; m < 32; m++) {
        const float p = __expf(a[m] - newM);
        S += p;
        const ull pp = pack2(p, p);
        const float* vr = &KV[hr * 1152 + m * 36];
#pragma unroll
        for (int i = 0; i < 8; i++) {
          const ulonglong2 v2 = *(const ulonglong2*)(vr + i * 4);
          fma2(acc2[2 * i], pp, v2.x);
          fma2(acc2[2 * i + 1], pp, v2.y);
        }
      }
      M = newM;
    }
  }

  // epilogue: heads row (hr, n0+ln)
  const float inv = 1.f / S;
  float* dst = &g_heads[((hr * kB + b) * kN + n0 + ln) * kd];
#pragma unroll
  for (int i = 0; i < 16; i++) {
    const float2 u = unpack2(acc2[i]);
    *(ull*)&dst[2 * i] = pack2(u.x * inv, u.y * inv);
  }
}

extern "C" void kernel_launch(void* const* d_in, const int* in_sizes, int n_in,
                              void* d_out, int out_size) {
  const float* h_fea = (const float*)d_in[0];
  const float* aux   = (const float*)d_in[1];
  const float* Wq    = (const float*)d_in[2];
  const float* Wk    = (const float*)d_in[3];
  const float* Wv    = (const float*)d_in[4];
  const float* W1    = (const float*)d_in[5];
  const float* b1    = (const float*)d_in[6];
  const float* W2    = (const float*)d_in[7];
  const float* b2    = (const float*)d_in[8];
  const float* Wout  = (const float*)d_in[9];
  float* out = (float*)d_out;
  float* out_aux = out + kHWaveElems;

  cudaFuncSetAttribute(fused_attn_kernel,
                       cudaFuncAttributeMaxDynamicSharedMemorySize,
                       (int)kFusedSmem);

  qkv_kernel<<<dim3(6, 128), 256>>>(h_fea, Wq, Wk, Wv);
  fused_attn_kernel<<<dim3(16, 32), 256, kFusedSmem>>>(aux, W1, b1, W2, b2,
                                                       out_aux);
  outproj_kernel<<<dim3(2, 128), 256>>>(Wout, out);
}

// round 7
// speedup vs baseline: 1.1460x; 1.1460x over previous
#include <cuda_runtime.h>

namespace {
constexpr int kH = 8;
constexpr int kB = 32;
constexpr int kN = 512;
constexpr int kD = 256;
constexpr int kd = 32;
constexpr int kBN = kB * kN;               // 16384
constexpr int kHWaveElems = kB * kN * kD;  // 4,194,304
// fused smem: Qs 8192 + KV 9216 + Sc 8448 + W1 256 + W2 128 + b1 16 + b2 8
constexpr int kFusedF = 8192 + 9216 + 8448 + 256 + 128 + 16 + 8;
constexpr size_t kFusedSmem = kFusedF * sizeof(float);  // 105056 B
}

using ull = unsigned long long;

__device__ __forceinline__ void fma2(ull& d, ull a, ull b) {
  asm("fma.rn.f32x2 %0, %1, %2, %0;" : "+l"(d) : "l"(a), "l"(b));
}
__device__ __forceinline__ void mul2(ull& d, ull a) {
  asm("mul.rn.f32x2 %0, %0, %1;" : "+l"(d) : "l"(a));
}
__device__ __forceinline__ ull pack2(float lo, float hi) {
  ull r;
  asm("mov.b64 %0, {%1, %2};" : "=l"(r) : "f"(lo), "f"(hi));
  return r;
}
__device__ __forceinline__ float2 unpack2(ull v) {
  float2 r;
  asm("mov.b64 {%0, %1}, %2;" : "=f"(r.x), "=f"(r.y) : "l"(v));
  return r;
}

// Scratch (device globals: allocation-free rule)
__device__ float g_Q[kH * kBN * kd];
__device__ float g_K[kH * kBN * kd];
__device__ float g_V[kH * kBN * kd];
__device__ float g_heads[kH * kBN * kd];

// ---------------------------------------------------------------------------
// GEMM body: 128x128 block, 256 threads, per-thread 8x8, k-chunk 16.
// ---------------------------------------------------------------------------
#define GEMM_DECL                                  \
  __shared__ __align__(16) float As[16 * 132];     \
  __shared__ __align__(16) float Bs[16 * 128];     \
  const int t = threadIdx.x;                       \
  const int tx = t & 15, ty = t >> 4;              \
  const int arow0 = t >> 2, akq0 = (t & 3) * 4;    \
  const int arow1 = arow0 + 64;                    \
  const int bkk0 = t >> 5, bc4 = (t & 31) * 4;     \
  const int bkk1 = bkk0 + 8;                       \
  ull acc2[8][4];                                  \
  _Pragma("unroll") for (int r = 0; r < 8; r++)    \
  _Pragma("unroll") for (int c = 0; c < 4; c++) acc2[r][c] = 0ULL;

#define GEMM_STS(ra0, ra1, rb0, rb1)                            \
  {                                                             \
    const float a0v[4] = {ra0.x, ra0.y, ra0.z, ra0.w};          \
    const float a1v[4] = {ra1.x, ra1.y, ra1.z, ra1.w};          \
    _Pragma("unroll") for (int j = 0; j < 4; j++) {             \
      As[(akq0 + j) * 132 + arow0] = a0v[j];                    \
      As[(akq0 + j) * 132 + arow1] = a1v[j];                    \
    }                                                           \
    *(float4*)&Bs[bkk0 * 128 + bc4] = rb0;                      \
    *(float4*)&Bs[bkk1 * 128 + bc4] = rb1;                      \
  }

#define GEMM_COMPUTE                                            \
  _Pragma("unroll") for (int kk = 0; kk < 16; kk++) {           \
    const float4 a0 = *(const float4*)&As[kk * 132 + ty * 8];   \
    const float4 a1 = *(const float4*)&As[kk * 132 + ty * 8 + 4]; \
    const ulonglong2 bq0 = *(const ulonglong2*)&Bs[kk * 128 + tx * 8]; \
    const ulonglong2 bq1 = *(const ulonglong2*)&Bs[kk * 128 + tx * 8 + 4]; \
    const float aa[8] = {a0.x, a0.y, a0.z, a0.w, a1.x, a1.y, a1.z, a1.w}; \
    _Pragma("unroll") for (int r = 0; r < 8; r++) {             \
      const ull ap = pack2(aa[r], aa[r]);                       \
      fma2(acc2[r][0], ap, bq0.x);                              \
      fma2(acc2[r][1], ap, bq0.y);                              \
      fma2(acc2[r][2], ap, bq1.x);                              \
      fma2(acc2[r][3], ap, bq1.y);                              \
    }                                                           \
  }

// ---------------------------------------------------------------------------
// K1: QKV projection [16384 x 256] x [256 x 768]. grid (6, 128).
// ---------------------------------------------------------------------------
__global__ __launch_bounds__(256, 2) void qkv_kernel(
    const float* __restrict__ A, const float* __restrict__ Wq,
    const float* __restrict__ Wk, const float* __restrict__ Wv) {
  GEMM_DECL
  const int c0 = blockIdx.x * 128;
  const int row0 = blockIdx.y * 128;
  const int which = c0 >> 8;
  const float* __restrict__ W = (which == 0) ? Wq : (which == 1) ? Wk : Wv;
  float* __restrict__ O = (which == 0) ? g_Q : (which == 1) ? g_K : g_V;

  const int bc = c0 + bc4;
  const int bh = (bc >> 5) & 7, bdd = bc & 31;

  float4 ra0 = *(const float4*)&A[(row0 + arow0) * kD + akq0];
  float4 ra1 = *(const float4*)&A[(row0 + arow1) * kD + akq0];
  float4 rb0 = *(const float4*)&W[(bh * 256 + bkk0) * kd + bdd];
  float4 rb1 = *(const float4*)&W[(bh * 256 + bkk1) * kd + bdd];

  for (int k0 = 0; k0 < kD; k0 += 16) {
    GEMM_STS(ra0, ra1, rb0, rb1)
    __syncthreads();
    if (k0 + 16 < kD) {
      ra0 = *(const float4*)&A[(row0 + arow0) * kD + k0 + 16 + akq0];
      ra1 = *(const float4*)&A[(row0 + arow1) * kD + k0 + 16 + akq0];
      rb0 = *(const float4*)&W[(bh * 256 + k0 + 16 + bkk0) * kd + bdd];
      rb1 = *(const float4*)&W[(bh * 256 + k0 + 16 + bkk1) * kd + bdd];
    }
    GEMM_COMPUTE
    __syncthreads();
  }

#pragma unroll
  for (int r = 0; r < 8; r++) {
    const int row = row0 + ty * 8 + r;
#pragma unroll
    for (int cp = 0; cp < 4; cp++) {
      const int oc = c0 + tx * 8 + 2 * cp;
      const int h = (oc >> 5) & 7, dd = oc & 31;
      *(ull*)&O[(h * kBN + row) * kd + dd] = acc2[r][cp];
    }
  }
}

// ---------------------------------------------------------------------------
// K3: output projection [16384 x 256] x [256 x 256]. grid (2, 128).
// ---------------------------------------------------------------------------
__global__ __launch_bounds__(256, 2) void outproj_kernel(
    const float* __restrict__ Wout, float* __restrict__ out) {
  GEMM_DECL
  const int c0 = blockIdx.x * 128;
  const int row0 = blockIdx.y * 128;

  auto ldA = [&](int row, int k) {
    const int h = k >> 5, dd = k & 31;
    return *(const float4*)&g_heads[(h * kBN + row0 + row) * kd + dd];
  };
  float4 ra0 = ldA(arow0, akq0);
  float4 ra1 = ldA(arow1, akq0);
  float4 rb0 = *(const float4*)&Wout[bkk0 * kD + c0 + bc4];
  float4 rb1 = *(const float4*)&Wout[bkk1 * kD + c0 + bc4];

  for (int k0 = 0; k0 < kD; k0 += 16) {
    GEMM_STS(ra0, ra1, rb0, rb1)
    __syncthreads();
    if (k0 + 16 < kD) {
      ra0 = ldA(arow0, k0 + 16 + akq0);
      ra1 = ldA(arow1, k0 + 16 + akq0);
      rb0 = *(const float4*)&Wout[(k0 + 16 + bkk0) * kD + c0 + bc4];
      rb1 = *(const float4*)&Wout[(k0 + 16 + bkk1) * kD + c0 + bc4];
    }
    GEMM_COMPUTE
    __syncthreads();
  }

#pragma unroll
  for (int r = 0; r < 8; r++) {
    const int row = row0 + ty * 8 + r;
#pragma unroll
    for (int cp = 0; cp < 4; cp++)
      *(ull*)&out[row * kD + c0 + tx * 8 + 2 * cp] = acc2[r][cp];
  }
}

// ---------------------------------------------------------------------------
// K2 (fused): scores + MLP + aux passthrough + ONLINE softmax + P@V.
// Round-7 fixes: (1) MLP in two passes of 2 positions -> reg peak <= 128
// (no local-memory spills under the (256,2) cap); (2) scores n-loop x2 with
// split accumulators (4 independent FMA chains); (3) PV m-loop unroll 2.
// ---------------------------------------------------------------------------
__global__ __launch_bounds__(256, 2) void fused_attn_kernel(
    const float* __restrict__ aux, const float* __restrict__ W1,
    const float* __restrict__ b1, const float* __restrict__ W2,
    const float* __restrict__ b2, float* __restrict__ out_aux) {
  extern __shared__ __align__(16) float sm[];
  float* Qs = sm;                 // [8][32][32]
  float* KV = sm + 8192;          // [8][32][36]
  float* Sc = sm + 8192 + 9216;   // [8][32][33]
  float* W1s = Sc + 8448;
  float* W2s = W1s + 256;
  float* b1s = W2s + 128;
  float* b2s = b1s + 16;
  const int n0 = blockIdx.x * 32;
  const int b = blockIdx.y;
  const int t = threadIdx.x;
  const int hr = t >> 5, ln = t & 31;  // role (h, m|n)
  const int nl = t >> 5, mm = t & 31;  // role (n-phase, m) for MLP

  // one-time loads
#pragma unroll
  for (int i = 0; i < 8; i++) {
    const int idx = t + 256 * i;
    const int h = idx >> 8, rem = idx & 255;
    const int n = rem >> 3, d4 = (rem & 7) * 4;
    *(float4*)&Qs[h * 1024 + n * 32 + d4] =
        *(const float4*)&g_Q[((h * kB + b) * kN + n0 + n) * kd + d4];
  }
  W1s[t] = W1[t];
  if (t < 128) W2s[t] = W2[t];
  if (t < 16) b1s[t] = b1[t];
  if (t < 8) b2s[t] = b2[t];

  float M = -1e30f, S = 0.f;
  ull acc2[16];
#pragma unroll
  for (int i = 0; i < 16; i++) acc2[i] = 0ULL;

#pragma unroll 1
  for (int ch = 0; ch < 16; ch++) {
    const int m0 = ch * 32;
    __syncthreads();  // KV & Sc reusable (prev chunk's PV done)
    // ---- load K chunk ----
#pragma unroll
    for (int i = 0; i < 8; i++) {
      const int idx = t + 256 * i;
      const int h = idx >> 8, rem = idx & 255;
      const int m = rem >> 3, d4 = (rem & 7) * 4;
      *(float4*)&KV[h * 1152 + m * 36 + d4] =
          *(const float4*)&g_K[((h * kB + b) * kN + m0 + m) * kd + d4];
    }
    __syncthreads();
    // ---- aux prefetch + passthrough (latency hidden under scores GEMM) ----
    float av[4][8];
#pragma unroll
    for (int p = 0; p < 4; p++) {
      const int n = nl + 8 * p;
#pragma unroll
      for (int h = 0; h < 8; h++) {
        const int gi = ((h * kB + b) * kN + n0 + n) * kN + m0 + mm;
        const float a = aux[gi];
        out_aux[gi] = a;
        av[p][h] = a;
      }
    }
    // ---- scores: role (hr, m=ln); n x2, split accumulators for ILP ----
    {
      ulonglong2 kr[8];
#pragma unroll
      for (int i = 0; i < 8; i++)
        kr[i] = *(const ulonglong2*)&KV[hr * 1152 + ln * 36 + i * 4];
#pragma unroll 1
      for (int n = 0; n < 32; n += 2) {
        const float* qp0 = &Qs[hr * 1024 + n * 32];
        const float* qp1 = qp0 + 32;
        ull s0a = 0ULL, s0b = 0ULL, s1a = 0ULL, s1b = 0ULL;
#pragma unroll
        for (int i = 0; i < 8; i++) {
          const ulonglong2 q0 = *(const ulonglong2*)(qp0 + i * 4);
          const ulonglong2 q1 = *(const ulonglong2*)(qp1 + i * 4);
          fma2(s0a, q0.x, kr[i].x);
          fma2(s0b, q0.y, kr[i].y);
          fma2(s1a, q1.x, kr[i].x);
          fma2(s1b, q1.y, kr[i].y);
        }
        const float2 u0a = unpack2(s0a), u0b = unpack2(s0b);
        const float2 u1a = unpack2(s1a), u1b = unpack2(s1b);
        Sc[hr * 1056 + n * 33 + ln] = (u0a.x + u0a.y) + (u0b.x + u0b.y);
        Sc[hr * 1056 + (n + 1) * 33 + ln] = (u1a.x + u1a.y) + (u1b.x + u1b.y);
      }
    }
    __syncthreads();
    // ---- MLP: role (nl, mm); TWO passes of 2 positions (reg-peak fix) ----
#pragma unroll
    for (int pp = 0; pp < 2; pp++) {
      ull hid2[2][8];
#pragma unroll
      for (int j2 = 0; j2 < 8; j2++) {
        const ull bp = *(const ull*)&b1s[2 * j2];
        hid2[0][j2] = bp;
        hid2[1][j2] = bp;
      }
#pragma unroll
      for (int i = 0; i < 16; i++) {
        ull xp[2];
#pragma unroll
        for (int q = 0; q < 2; q++) {
          const int p = 2 * pp + q;
          const float xv = (i < 8) ? Sc[i * 1056 + (nl + 8 * p) * 33 + mm]
                                   : av[p][i - 8];
          xp[q] = pack2(xv, xv);
        }
#pragma unroll
        for (int j2 = 0; j2 < 8; j2++) {
          const ull w2 = *(const ull*)&W1s[i * 16 + 2 * j2];
          fma2(hid2[0][j2], xp[0], w2);
          fma2(hid2[1][j2], xp[1], w2);
        }
      }
      ull o2[2][4];
#pragma unroll
      for (int k2 = 0; k2 < 4; k2++) {
        const ull bp = *(const ull*)&b2s[2 * k2];
        o2[0][k2] = bp;
        o2[1][k2] = bp;
      }
#pragma unroll
      for (int j2 = 0; j2 < 8; j2++) {
#pragma unroll
        for (int q = 0; q < 2; q++) {
          float2 hv = unpack2(hid2[q][j2]);
          hv.x = fmaxf(hv.x, 0.f);
          hv.y = fmaxf(hv.y, 0.f);
          const ull hp0 = pack2(hv.x, hv.x);
          const ull hp1 = pack2(hv.y, hv.y);
#pragma unroll
          for (int k2 = 0; k2 < 4; k2++) {
            fma2(o2[q][k2], hp0, *(const ull*)&W2s[(2 * j2) * 8 + 2 * k2]);
            fma2(o2[q][k2], hp1, *(const ull*)&W2s[(2 * j2 + 1) * 8 + 2 * k2]);
          }
        }
      }
#pragma unroll
      for (int q = 0; q < 2; q++) {
        const int n = nl + 8 * (2 * pp + q);
#pragma unroll
        for (int k2 = 0; k2 < 4; k2++) {
          const float2 ov = unpack2(o2[q][k2]);
          Sc[(2 * k2) * 1056 + n * 33 + mm] = ov.x;
          Sc[(2 * k2 + 1) * 1056 + n * 33 + mm] = ov.y;
        }
      }
    }
    // ---- load V chunk ----
#pragma unroll
    for (int i = 0; i < 8; i++) {
      const int idx = t + 256 * i;
      const int h = idx >> 8, rem = idx & 255;
      const int m = rem >> 3, d4 = (rem & 7) * 4;
      *(float4*)&KV[h * 1152 + m * 36 + d4] =
          *(const float4*)&g_V[((h * kB + b) * kN + m0 + m) * kd + d4];
    }
    __syncthreads();  // V + MLP logits visible
    // ---- online softmax + PV: role (hr, n=ln) ----
    {
      float a[32];
#pragma unroll
      for (int i = 0; i < 32; i++) a[i] = Sc[hr * 1056 + ln * 33 + i];
      float cm = a[0];
#pragma unroll
      for (int i = 1; i < 32; i++) cm = fmaxf(cm, a[i]);
      const float newM = fmaxf(M, cm);
      const float sc = __expf(M - newM);
      S *= sc;
      const ull scp = pack2(sc, sc);
#pragma unroll
      for (int i = 0; i < 16; i++) mul2(acc2[i], scp);
#pragma unroll 2
      for (int m = 0; m < 32; m++) {
        const float p = __expf(a[m] - newM);
        S += p;
        const ull pp = pack2(p, p);
        const float* vr = &KV[hr * 1152 + m * 36];
#pragma unroll
        for (int i = 0; i < 8; i++) {
          const ulonglong2 v2 = *(const ulonglong2*)(vr + i * 4);
          fma2(acc2[2 * i], pp, v2.x);
          fma2(acc2[2 * i + 1], pp, v2.y);
        }
      }
      M = newM;
    }
  }

  // epilogue: heads row (hr, n0+ln)
  const float inv = 1.f / S;
  float* dst = &g_heads[((hr * kB + b) * kN + n0 + ln) * kd];
#pragma unroll
  for (int i = 0; i < 16; i++) {
    const float2 u = unpack2(acc2[i]);
    *(ull*)&dst[2 * i] = pack2(u.x * inv, u.y * inv);
  }
}

extern "C" void kernel_launch(void* const* d_in, const int* in_sizes, int n_in,
                              void* d_out, int out_size) {
  const float* h_fea = (const float*)d_in[0];
  const float* aux   = (const float*)d_in[1];
  const float* Wq    = (const float*)d_in[2];
  const float* Wk    = (const float*)d_in[3];
  const float* Wv    = (const float*)d_in[4];
  const float* W1    = (const float*)d_in[5];
  const float* b1    = (const float*)d_in[6];
  const float* W2    = (const float*)d_in[7];
  const float* b2    = (const float*)d_in[8];
  const float* Wout  = (const float*)d_in[9];
  float* out = (float*)d_out;
  float* out_aux = out + kHWaveElems;

  cudaFuncSetAttribute(fused_attn_kernel,
                       cudaFuncAttributeMaxDynamicSharedMemorySize,
                       (int)kFusedSmem);

  qkv_kernel<<<dim3(6, 128), 256>>>(h_fea, Wq, Wk, Wv);
  fused_attn_kernel<<<dim3(16, 32), 256, kFusedSmem>>>(aux, W1, b1, W2, b2,
                                                       out_aux);
  outproj_kernel<<<dim3(2, 128), 256>>>(Wout, out);
}